// round 13
// baseline (speedup 1.0000x reference)
#include <cuda_runtime.h>
#include <cuda_fp16.h>
#include <cstdint>

// ---------------------------------------------------------------------------
// MoE layer: B=4,S=2048,D=1024,E=8,F=4096, top-k=2
// Round 11: R10 GEMM (2 CTAs/SM) + combine fused into GEMM2 epilogue via
// deterministic 2-add atomicAdd; zeropad+combine kernels and g_y deleted.
// ---------------------------------------------------------------------------

#define T_TOK   8192
#define DDIM    1024
#define EEXP    8
#define FDIM    4096
#define NASSIGN (T_TOK * 2)
#define SEGPAD  128
#define MAXSLOTS (NASSIGN + EEXP * SEGPAD)  // 17408

__device__ __half g_xph[MAXSLOTS * (size_t)DDIM];
__device__ __half g_h  [MAXSLOTS * (size_t)FDIM];
__device__ __half g_w1h[(size_t)EEXP * DDIM * FDIM];
__device__ __half g_w2h[(size_t)EEXP * FDIM * DDIM];
__device__ int   g_te[NASSIGN];
__device__ float g_tw[NASSIGN];
__device__ int   g_inv[MAXSLOTS];   // slot -> assignment index (-1 = pad)
__device__ int   g_count[EEXP];
__device__ int   g_cursor[EEXP];
__device__ int   g_offs[EEXP + 1];

__device__ __forceinline__ uint32_t smem_u32(const void* p) {
    uint32_t a;
    asm("{ .reg .u64 t; cvta.to.shared.u64 t, %1; cvt.u32.u64 %0, t; }" : "=r"(a) : "l"(p));
    return a;
}
#define CP_ASYNC16(dst, src) \
    asm volatile("cp.async.cg.shared.global [%0], [%1], 16;" :: "r"(dst), "l"(src) : "memory")
#define CP_COMMIT() asm volatile("cp.async.commit_group;" ::: "memory")
#define CP_WAIT(n)  asm volatile("cp.async.wait_group %0;" :: "n"(n) : "memory")

__device__ __forceinline__ void mma_f16(float* d, const uint32_t* a, const uint32_t* b) {
    asm volatile(
        "mma.sync.aligned.m16n8k16.row.col.f32.f16.f16.f32 "
        "{%0,%1,%2,%3}, {%4,%5,%6,%7}, {%8,%9}, {%0,%1,%2,%3};"
        : "+f"(d[0]), "+f"(d[1]), "+f"(d[2]), "+f"(d[3])
        : "r"(a[0]), "r"(a[1]), "r"(a[2]), "r"(a[3]), "r"(b[0]), "r"(b[1]));
}
__device__ __forceinline__ void ldsm_x4(uint32_t* r, uint32_t addr) {
    asm volatile("ldmatrix.sync.aligned.m8n8.x4.shared.b16 {%0,%1,%2,%3}, [%4];"
        : "=r"(r[0]), "=r"(r[1]), "=r"(r[2]), "=r"(r[3]) : "r"(addr));
}
__device__ __forceinline__ void ldsm_x4_t(uint32_t* r, uint32_t addr) {
    asm volatile("ldmatrix.sync.aligned.m8n8.x4.trans.shared.b16 {%0,%1,%2,%3}, [%4];"
        : "=r"(r[0]), "=r"(r[1]), "=r"(r[2]), "=r"(r[3]) : "r"(addr));
}

// ---------------------------------------------------------------------------
// init: zero counts/cursors, set g_inv = -1 everywhere.
__global__ void k_init() {
    int i = blockIdx.x * 256 + threadIdx.x;
    if (i < EEXP) { g_count[i] = 0; g_cursor[i] = 0; }
    if (i < MAXSLOTS) g_inv[i] = -1;
}

// Gate: one warp per token (fp32).
__global__ void k_gate(const float* __restrict__ x, const float* __restrict__ Wg) {
    int t = blockIdx.x * 8 + (threadIdx.x >> 5);
    int lane = threadIdx.x & 31;
    const float* xr = x + (size_t)t * DDIM;

    float acc[EEXP];
#pragma unroll
    for (int e = 0; e < EEXP; e++) acc[e] = 0.f;
#pragma unroll 4
    for (int i = 0; i < DDIM / 32; i++) {
        int d = i * 32 + lane;
        float xv = xr[d];
        const float4* wr = (const float4*)(Wg + (size_t)d * EEXP);
        float4 w0 = wr[0], w1 = wr[1];
        acc[0] += xv * w0.x; acc[1] += xv * w0.y;
        acc[2] += xv * w0.z; acc[3] += xv * w0.w;
        acc[4] += xv * w1.x; acc[5] += xv * w1.y;
        acc[6] += xv * w1.z; acc[7] += xv * w1.w;
    }
#pragma unroll
    for (int off = 16; off > 0; off >>= 1)
#pragma unroll
        for (int e = 0; e < EEXP; e++)
            acc[e] += __shfl_xor_sync(0xffffffffu, acc[e], off);

    if (lane == 0) {
        int i1 = 0;
#pragma unroll
        for (int e = 1; e < EEXP; e++) if (acc[e] > acc[i1]) i1 = e;
        int i2 = -1;
#pragma unroll
        for (int e = 0; e < EEXP; e++) {
            if (e == i1) continue;
            if (i2 < 0 || acc[e] > acc[i2]) i2 = e;
        }
        float wa = 1.f / (1.f + expf(acc[i2] - acc[i1]));
        g_te[2 * t] = i1;  g_te[2 * t + 1] = i2;
        g_tw[2 * t] = wa;  g_tw[2 * t + 1] = 1.f - wa;
        atomicAdd(&g_count[i1], 1);
        atomicAdd(&g_count[i2], 1);
    }
}

__global__ void k_offs() {
    if (threadIdx.x == 0) {
        int o = 0;
#pragma unroll
        for (int e = 0; e < EEXP; e++) {
            g_offs[e] = o;
            o += (g_count[e] + SEGPAD - 1) & ~(SEGPAD - 1);
            g_cursor[e] = 0;
        }
        g_offs[EEXP] = o;
    }
}

// Convert fp32 weights -> fp16 (RN).
__global__ void k_cvt(const float4* __restrict__ src, uint2* __restrict__ dst) {
    int i = blockIdx.x * 256 + threadIdx.x;
    float4 v = src[i];
    __half2 h01 = __floats2half2_rn(v.x, v.y);
    __half2 h23 = __floats2half2_rn(v.z, v.w);
    uint2 u;
    u.x = *(uint32_t*)&h01;
    u.y = *(uint32_t*)&h23;
    dst[i] = u;
}

// Gather: permute + convert x row to fp16; record inverse map.
__global__ void k_gather(const float* __restrict__ x) {
    int a = blockIdx.x * 8 + (threadIdx.x >> 5);
    int lane = threadIdx.x & 31;
    if (a >= NASSIGN) return;
    int t = a >> 1;
    int e = g_te[a];
    int slot = 0;
    if (lane == 0) {
        slot = g_offs[e] + atomicAdd(&g_cursor[e], 1);
        g_inv[slot] = a;
    }
    slot = __shfl_sync(0xffffffffu, slot, 0);
    const float4* src = (const float4*)(x + (size_t)t * DDIM);
    uint2* dst = (uint2*)(g_xph + (size_t)slot * DDIM);
#pragma unroll
    for (int i = 0; i < 8; i++) {
        float4 v = src[lane + 32 * i];
        __half2 h01 = __floats2half2_rn(v.x, v.y);
        __half2 h23 = __floats2half2_rn(v.z, v.w);
        uint2 u;
        u.x = *(uint32_t*)&h01;
        u.y = *(uint32_t*)&h23;
        dst[lane + 32 * i] = u;
    }
}

__device__ __forceinline__ float gelu_tanh(float v) {
    float v3 = v * v * v;
    return 0.5f * v * (1.f + tanhf(0.7978845608028654f * (v + 0.044715f * v3)));
}

// ---------------------------------------------------------------------------
// fp16 mma GEMM, 256 threads, 2 CTAs/SM. BM=128, BN=128, BK=64 halves.
// doGelu=1: writes gelu(h) fp16 to g_h. doGelu=0: scatters w*acc into out
// via atomicAdd (exactly 2 commutative adds per element -> deterministic).
#define BM 128
#define BN 128
#define BKF 64
#define NSTAGE 2
#define ATILE_B (BM * 72 * 2)        // 18432 B
#define BTILE_B (BKF * 136 * 2)      // 17408 B
#define SMEM_GEMM (NSTAGE * (ATILE_B + BTILE_B))  // 71680 B

__global__ __launch_bounds__(256, 2)
void k_gemm_h(const __half* __restrict__ A, const __half* __restrict__ W,
              float* __restrict__ out, int K, int Ntot, int doGelu) {
    int row0 = blockIdx.x * BM;
    if (row0 >= g_offs[EEXP]) return;
    int e = 0;
    while (g_offs[e + 1] <= row0) e++;

    extern __shared__ char smem[];
    uint32_t sbase = smem_u32(smem);

    int tid = threadIdx.x, wid = tid >> 5, lane = tid & 31;
    int gid = lane >> 2, tig = lane & 3;
    int warp_m = wid & 1, warp_n = wid >> 1;   // 2 x 4 warps, warp tile 64x32

    const __half* B = W + (size_t)e * K * Ntot + (size_t)blockIdx.y * BN;

    int ar = tid >> 3, ach = tid & 7;
    const __half* asrc = A + (size_t)(row0 + ar) * K + ach * 8;
    uint32_t a_d = sbase + (uint32_t)ar * 144 + (uint32_t)ach * 16;
    int br = tid >> 4, bch = tid & 15;
    const __half* bsrc = B + (size_t)br * Ntot + bch * 8;
    uint32_t b_d = sbase + (uint32_t)NSTAGE * ATILE_B + (uint32_t)br * 272 + (uint32_t)bch * 16;

    uint32_t a_lm = sbase + ((uint32_t)(warp_m * 64 + (lane & 15))) * 144 + ((lane >> 4) << 4);
    uint32_t b_row = (lane & 7) + ((lane >> 3) & 1) * 8;
    uint32_t b_ncol = (uint32_t)(warp_n * 32) + ((lane >> 4) << 3);
    uint32_t b_lm = sbase + (uint32_t)NSTAGE * ATILE_B + b_row * 272 + b_ncol * 2;

    float acc[4][4][4];
#pragma unroll
    for (int mt = 0; mt < 4; mt++)
#pragma unroll
        for (int nt = 0; nt < 4; nt++)
#pragma unroll
            for (int j = 0; j < 4; j++) acc[mt][nt][j] = 0.f;

    int KT = K / BKF;

#define LOAD_TILE(kt, st) do { \
    int _k0 = (kt) * BKF; \
    uint32_t _ao = (uint32_t)(st) * ATILE_B; \
    uint32_t _bo = (uint32_t)(st) * BTILE_B; \
    CP_ASYNC16(a_d + _ao,                  asrc + _k0); \
    CP_ASYNC16(a_d + _ao + 32u * 144,      asrc + _k0 + (size_t)32 * K); \
    CP_ASYNC16(a_d + _ao + 64u * 144,      asrc + _k0 + (size_t)64 * K); \
    CP_ASYNC16(a_d + _ao + 96u * 144,      asrc + _k0 + (size_t)96 * K); \
    CP_ASYNC16(b_d + _bo,                  bsrc + (size_t)_k0 * Ntot); \
    CP_ASYNC16(b_d + _bo + 16u * 272,      bsrc + (size_t)(_k0 + 16) * Ntot); \
    CP_ASYNC16(b_d + _bo + 32u * 272,      bsrc + (size_t)(_k0 + 32) * Ntot); \
    CP_ASYNC16(b_d + _bo + 48u * 272,      bsrc + (size_t)(_k0 + 48) * Ntot); \
} while (0)

    LOAD_TILE(0, 0); CP_COMMIT();

    for (int kt = 0; kt < KT; kt++) {
        int stage = kt & 1;
        CP_WAIT(0);
        __syncthreads();
        if (kt + 1 < KT) {
            LOAD_TILE(kt + 1, stage ^ 1);
            CP_COMMIT();
        }

        uint32_t a_s = a_lm + (uint32_t)stage * ATILE_B;
        uint32_t b_s = b_lm + (uint32_t)stage * BTILE_B;
#pragma unroll
        for (int ks = 0; ks < 4; ks++) {
            uint32_t afrag[4][4];
#pragma unroll
            for (int mt = 0; mt < 4; mt++)
                ldsm_x4(afrag[mt], a_s + (uint32_t)mt * 16 * 144 + (uint32_t)ks * 32);
            uint32_t bfrag[4][2];
#pragma unroll
            for (int nt2 = 0; nt2 < 2; nt2++) {
                uint32_t r[4];
                ldsm_x4_t(r, b_s + (uint32_t)ks * 16 * 272 + (uint32_t)nt2 * 32);
                bfrag[2 * nt2][0] = r[0]; bfrag[2 * nt2][1] = r[1];
                bfrag[2 * nt2 + 1][0] = r[2]; bfrag[2 * nt2 + 1][1] = r[3];
            }
#pragma unroll
            for (int mt = 0; mt < 4; mt++)
#pragma unroll
                for (int nt = 0; nt < 4; nt++)
                    mma_f16(acc[mt][nt], afrag[mt], bfrag[nt]);
        }
    }

    // epilogue
#pragma unroll
    for (int mt = 0; mt < 4; mt++) {
        int mrow = row0 + warp_m * 64 + mt * 16 + gid;
        if (doGelu) {
#pragma unroll
            for (int nt = 0; nt < 4; nt++) {
                int col = blockIdx.y * BN + warp_n * 32 + nt * 8 + 2 * tig;
                __half2 h0 = __floats2half2_rn(gelu_tanh(acc[mt][nt][0]),
                                               gelu_tanh(acc[mt][nt][1]));
                __half2 h1 = __floats2half2_rn(gelu_tanh(acc[mt][nt][2]),
                                               gelu_tanh(acc[mt][nt][3]));
                *(__half2*)(g_h + (size_t)mrow * Ntot + col) = h0;
                *(__half2*)(g_h + (size_t)(mrow + 8) * Ntot + col) = h1;
            }
        } else {
            int a0 = g_inv[mrow], a1 = g_inv[mrow + 8];
            float w0 = 0.f, w1 = 0.f;
            size_t o0 = 0, o1 = 0;
            if (a0 >= 0) { w0 = g_tw[a0]; o0 = (size_t)(a0 >> 1) * DDIM; }
            if (a1 >= 0) { w1 = g_tw[a1]; o1 = (size_t)(a1 >> 1) * DDIM; }
#pragma unroll
            for (int nt = 0; nt < 4; nt++) {
                int col = blockIdx.y * BN + warp_n * 32 + nt * 8 + 2 * tig;
                if (a0 >= 0) {
                    atomicAdd(out + o0 + col,     w0 * acc[mt][nt][0]);
                    atomicAdd(out + o0 + col + 1, w0 * acc[mt][nt][1]);
                }
                if (a1 >= 0) {
                    atomicAdd(out + o1 + col,     w1 * acc[mt][nt][2]);
                    atomicAdd(out + o1 + col + 1, w1 * acc[mt][nt][3]);
                }
            }
        }
    }
}

// ---------------------------------------------------------------------------
extern "C" void kernel_launch(void* const* d_in, const int* in_sizes, int n_in,
                              void* d_out, int out_size) {
    const float* x  = (const float*)d_in[0];
    const float* Wg = (const float*)d_in[1];
    const float* w1 = (const float*)d_in[2];
    const float* w2 = (const float*)d_in[3];
    float* out = (float*)d_out;

    cudaFuncSetAttribute(k_gemm_h, cudaFuncAttributeMaxDynamicSharedMemorySize, SMEM_GEMM);

    __half* w1h; cudaGetSymbolAddress((void**)&w1h, g_w1h);
    __half* w2h; cudaGetSymbolAddress((void**)&w2h, g_w2h);
    __half* xph; cudaGetSymbolAddress((void**)&xph, g_xph);
    __half* hbuf; cudaGetSymbolAddress((void**)&hbuf, g_h);

    cudaMemsetAsync(out, 0, (size_t)out_size * sizeof(float));

    k_init<<<(MAXSLOTS + 255) / 256, 256>>>();
    k_gate<<<T_TOK / 8, 256>>>(x, Wg);
    k_offs<<<1, 32>>>();

    int n4 = EEXP * DDIM * FDIM / 4;
    k_cvt<<<n4 / 256, 256>>>((const float4*)w1, (uint2*)w1h);
    k_cvt<<<n4 / 256, 256>>>((const float4*)w2, (uint2*)w2h);

    k_gather<<<NASSIGN / 8, 256>>>(x);

    dim3 grid1(MAXSLOTS / BM, FDIM / BN);   // (136, 32)
    k_gemm_h<<<grid1, 256, SMEM_GEMM>>>(xph, w1h, nullptr, DDIM, FDIM, 1);

    dim3 grid2(MAXSLOTS / BM, DDIM / BN);   // (136, 8)
    k_gemm_h<<<grid2, 256, SMEM_GEMM>>>(hbuf, w2h, out, FDIM, DDIM, 0);
}

// round 14
// speedup vs baseline: 1.0161x; 1.0161x over previous
#include <cuda_runtime.h>
#include <cuda_fp16.h>
#include <cstdint>

// ---------------------------------------------------------------------------
// MoE layer: B=4,S=2048,D=1024,E=8,F=4096, top-k=2
// Round 13: merged cvt + init-zeroes-out (no memset node) so GEMM1 is the
// 6th launch (ncu -s 5 captures it); B-fragment register prefetch.
// ---------------------------------------------------------------------------

#define T_TOK   8192
#define DDIM    1024
#define EEXP    8
#define FDIM    4096
#define NASSIGN (T_TOK * 2)
#define SEGPAD  128
#define MAXSLOTS (NASSIGN + EEXP * SEGPAD)  // 17408
#define OUT_ELEMS (T_TOK * DDIM)            // 8388608

__device__ __half g_xph[MAXSLOTS * (size_t)DDIM];
__device__ __half g_h  [MAXSLOTS * (size_t)FDIM];
__device__ __half g_w1h[(size_t)EEXP * DDIM * FDIM];
__device__ __half g_w2h[(size_t)EEXP * FDIM * DDIM];
__device__ int   g_te[NASSIGN];
__device__ float g_tw[NASSIGN];
__device__ int   g_inv[MAXSLOTS];   // slot -> assignment index (-1 = pad)
__device__ int   g_count[EEXP];
__device__ int   g_cursor[EEXP];
__device__ int   g_offs[EEXP + 1];

__device__ __forceinline__ uint32_t smem_u32(const void* p) {
    uint32_t a;
    asm("{ .reg .u64 t; cvta.to.shared.u64 t, %1; cvt.u32.u64 %0, t; }" : "=r"(a) : "l"(p));
    return a;
}
#define CP_ASYNC16(dst, src) \
    asm volatile("cp.async.cg.shared.global [%0], [%1], 16;" :: "r"(dst), "l"(src) : "memory")
#define CP_COMMIT() asm volatile("cp.async.commit_group;" ::: "memory")
#define CP_WAIT(n)  asm volatile("cp.async.wait_group %0;" :: "n"(n) : "memory")

__device__ __forceinline__ void mma_f16(float* d, const uint32_t* a, const uint32_t* b) {
    asm volatile(
        "mma.sync.aligned.m16n8k16.row.col.f32.f16.f16.f32 "
        "{%0,%1,%2,%3}, {%4,%5,%6,%7}, {%8,%9}, {%0,%1,%2,%3};"
        : "+f"(d[0]), "+f"(d[1]), "+f"(d[2]), "+f"(d[3])
        : "r"(a[0]), "r"(a[1]), "r"(a[2]), "r"(a[3]), "r"(b[0]), "r"(b[1]));
}
__device__ __forceinline__ void ldsm_x4(uint32_t* r, uint32_t addr) {
    asm volatile("ldmatrix.sync.aligned.m8n8.x4.shared.b16 {%0,%1,%2,%3}, [%4];"
        : "=r"(r[0]), "=r"(r[1]), "=r"(r[2]), "=r"(r[3]) : "r"(addr));
}
__device__ __forceinline__ void ldsm_x4_t(uint32_t* r, uint32_t addr) {
    asm volatile("ldmatrix.sync.aligned.m8n8.x4.trans.shared.b16 {%0,%1,%2,%3}, [%4];"
        : "=r"(r[0]), "=r"(r[1]), "=r"(r[2]), "=r"(r[3]) : "r"(addr));
}

// ---------------------------------------------------------------------------
// Merged weight conversion: both w1 and w2 in one launch.
#define CVT_N4 (EEXP * DDIM * FDIM / 4)   // float4 count per weight tensor
__global__ void k_cvt2(const float4* __restrict__ s1, uint2* __restrict__ d1,
                       const float4* __restrict__ s2, uint2* __restrict__ d2) {
    int i = blockIdx.x * 256 + threadIdx.x;
    const float4* s = (i < CVT_N4) ? s1 : s2;
    uint2* d = (i < CVT_N4) ? d1 : d2;
    int j = (i < CVT_N4) ? i : i - CVT_N4;
    float4 v = s[j];
    __half2 h01 = __floats2half2_rn(v.x, v.y);
    __half2 h23 = __floats2half2_rn(v.z, v.w);
    uint2 u;
    u.x = *(uint32_t*)&h01;
    u.y = *(uint32_t*)&h23;
    d[j] = u;
}

// init: zero counts/cursors, g_inv = -1, and zero the output buffer.
__global__ void k_init(float4* __restrict__ out4) {
    int i = blockIdx.x * 256 + threadIdx.x;
    if (i < EEXP) { g_count[i] = 0; g_cursor[i] = 0; }
    if (i < MAXSLOTS) g_inv[i] = -1;
    if (i < OUT_ELEMS / 4) out4[i] = make_float4(0.f, 0.f, 0.f, 0.f);
}

// Gate: one warp per token (fp32).
__global__ void k_gate(const float* __restrict__ x, const float* __restrict__ Wg) {
    int t = blockIdx.x * 8 + (threadIdx.x >> 5);
    int lane = threadIdx.x & 31;
    const float* xr = x + (size_t)t * DDIM;

    float acc[EEXP];
#pragma unroll
    for (int e = 0; e < EEXP; e++) acc[e] = 0.f;
#pragma unroll 4
    for (int i = 0; i < DDIM / 32; i++) {
        int d = i * 32 + lane;
        float xv = xr[d];
        const float4* wr = (const float4*)(Wg + (size_t)d * EEXP);
        float4 w0 = wr[0], w1 = wr[1];
        acc[0] += xv * w0.x; acc[1] += xv * w0.y;
        acc[2] += xv * w0.z; acc[3] += xv * w0.w;
        acc[4] += xv * w1.x; acc[5] += xv * w1.y;
        acc[6] += xv * w1.z; acc[7] += xv * w1.w;
    }
#pragma unroll
    for (int off = 16; off > 0; off >>= 1)
#pragma unroll
        for (int e = 0; e < EEXP; e++)
            acc[e] += __shfl_xor_sync(0xffffffffu, acc[e], off);

    if (lane == 0) {
        int i1 = 0;
#pragma unroll
        for (int e = 1; e < EEXP; e++) if (acc[e] > acc[i1]) i1 = e;
        int i2 = -1;
#pragma unroll
        for (int e = 0; e < EEXP; e++) {
            if (e == i1) continue;
            if (i2 < 0 || acc[e] > acc[i2]) i2 = e;
        }
        float wa = 1.f / (1.f + expf(acc[i2] - acc[i1]));
        g_te[2 * t] = i1;  g_te[2 * t + 1] = i2;
        g_tw[2 * t] = wa;  g_tw[2 * t + 1] = 1.f - wa;
        atomicAdd(&g_count[i1], 1);
        atomicAdd(&g_count[i2], 1);
    }
}

__global__ void k_offs() {
    if (threadIdx.x == 0) {
        int o = 0;
#pragma unroll
        for (int e = 0; e < EEXP; e++) {
            g_offs[e] = o;
            o += (g_count[e] + SEGPAD - 1) & ~(SEGPAD - 1);
            g_cursor[e] = 0;
        }
        g_offs[EEXP] = o;
    }
}

// Gather: permute + convert x row to fp16; record inverse map.
__global__ void k_gather(const float* __restrict__ x) {
    int a = blockIdx.x * 8 + (threadIdx.x >> 5);
    int lane = threadIdx.x & 31;
    if (a >= NASSIGN) return;
    int t = a >> 1;
    int e = g_te[a];
    int slot = 0;
    if (lane == 0) {
        slot = g_offs[e] + atomicAdd(&g_cursor[e], 1);
        g_inv[slot] = a;
    }
    slot = __shfl_sync(0xffffffffu, slot, 0);
    const float4* src = (const float4*)(x + (size_t)t * DDIM);
    uint2* dst = (uint2*)(g_xph + (size_t)slot * DDIM);
#pragma unroll
    for (int i = 0; i < 8; i++) {
        float4 v = src[lane + 32 * i];
        __half2 h01 = __floats2half2_rn(v.x, v.y);
        __half2 h23 = __floats2half2_rn(v.z, v.w);
        uint2 u;
        u.x = *(uint32_t*)&h01;
        u.y = *(uint32_t*)&h23;
        dst[lane + 32 * i] = u;
    }
}

__device__ __forceinline__ float gelu_tanh(float v) {
    float v3 = v * v * v;
    return 0.5f * v * (1.f + tanhf(0.7978845608028654f * (v + 0.044715f * v3)));
}

// ---------------------------------------------------------------------------
// fp16 mma GEMM, 256 threads, 2 CTAs/SM. BM=128, BN=128, BK=64 halves.
// B-fragment register prefetch (bfrag[2]); A fragments just-in-time.
#define BM 128
#define BN 128
#define BKF 64
#define NSTAGE 2
#define ATILE_B (BM * 72 * 2)        // 18432 B
#define BTILE_B (BKF * 136 * 2)      // 17408 B
#define SMEM_GEMM (NSTAGE * (ATILE_B + BTILE_B))  // 71680 B

__global__ __launch_bounds__(256, 2)
void k_gemm_h(const __half* __restrict__ A, const __half* __restrict__ W,
              float* __restrict__ out, int K, int Ntot, int doGelu) {
    int row0 = blockIdx.x * BM;
    if (row0 >= g_offs[EEXP]) return;
    int e = 0;
    while (g_offs[e + 1] <= row0) e++;

    extern __shared__ char smem[];
    uint32_t sbase = smem_u32(smem);

    int tid = threadIdx.x, wid = tid >> 5, lane = tid & 31;
    int gid = lane >> 2, tig = lane & 3;
    int warp_m = wid & 1, warp_n = wid >> 1;   // 2 x 4 warps, warp tile 64x32

    const __half* B = W + (size_t)e * K * Ntot + (size_t)blockIdx.y * BN;

    int ar = tid >> 3, ach = tid & 7;
    const __half* asrc = A + (size_t)(row0 + ar) * K + ach * 8;
    uint32_t a_d = sbase + (uint32_t)ar * 144 + (uint32_t)ach * 16;
    int br = tid >> 4, bch = tid & 15;
    const __half* bsrc = B + (size_t)br * Ntot + bch * 8;
    uint32_t b_d = sbase + (uint32_t)NSTAGE * ATILE_B + (uint32_t)br * 272 + (uint32_t)bch * 16;

    uint32_t a_lm = sbase + ((uint32_t)(warp_m * 64 + (lane & 15))) * 144 + ((lane >> 4) << 4);
    uint32_t b_row = (lane & 7) + ((lane >> 3) & 1) * 8;
    uint32_t b_ncol = (uint32_t)(warp_n * 32) + ((lane >> 4) << 3);
    uint32_t b_lm = sbase + (uint32_t)NSTAGE * ATILE_B + b_row * 272 + b_ncol * 2;

    float acc[4][4][4];
#pragma unroll
    for (int mt = 0; mt < 4; mt++)
#pragma unroll
        for (int nt = 0; nt < 4; nt++)
#pragma unroll
            for (int j = 0; j < 4; j++) acc[mt][nt][j] = 0.f;

    int KT = K / BKF;

#define LOAD_TILE(kt, st) do { \
    int _k0 = (kt) * BKF; \
    uint32_t _ao = (uint32_t)(st) * ATILE_B; \
    uint32_t _bo = (uint32_t)(st) * BTILE_B; \
    CP_ASYNC16(a_d + _ao,                  asrc + _k0); \
    CP_ASYNC16(a_d + _ao + 32u * 144,      asrc + _k0 + (size_t)32 * K); \
    CP_ASYNC16(a_d + _ao + 64u * 144,      asrc + _k0 + (size_t)64 * K); \
    CP_ASYNC16(a_d + _ao + 96u * 144,      asrc + _k0 + (size_t)96 * K); \
    CP_ASYNC16(b_d + _bo,                  bsrc + (size_t)_k0 * Ntot); \
    CP_ASYNC16(b_d + _bo + 16u * 272,      bsrc + (size_t)(_k0 + 16) * Ntot); \
    CP_ASYNC16(b_d + _bo + 32u * 272,      bsrc + (size_t)(_k0 + 32) * Ntot); \
    CP_ASYNC16(b_d + _bo + 48u * 272,      bsrc + (size_t)(_k0 + 48) * Ntot); \
} while (0)

// load B fragments for k16-step ks into buffer buf
#define LDB(buf, b_s, ks) do { \
    _Pragma("unroll") \
    for (int _n2 = 0; _n2 < 2; _n2++) { \
        uint32_t _r[4]; \
        ldsm_x4_t(_r, (b_s) + (uint32_t)(ks) * 16 * 272 + (uint32_t)_n2 * 32); \
        bfrag[buf][2 * _n2][0] = _r[0]; bfrag[buf][2 * _n2][1] = _r[1]; \
        bfrag[buf][2 * _n2 + 1][0] = _r[2]; bfrag[buf][2 * _n2 + 1][1] = _r[3]; \
    } \
} while (0)

    LOAD_TILE(0, 0); CP_COMMIT();

    uint32_t bfrag[2][4][2];

    for (int kt = 0; kt < KT; kt++) {
        int stage = kt & 1;
        CP_WAIT(0);
        __syncthreads();
        if (kt + 1 < KT) {
            LOAD_TILE(kt + 1, stage ^ 1);
            CP_COMMIT();
        }

        uint32_t a_s = a_lm + (uint32_t)stage * ATILE_B;
        uint32_t b_s = b_lm + (uint32_t)stage * BTILE_B;

        LDB(0, b_s, 0);
#pragma unroll
        for (int ks = 0; ks < 4; ks++) {
            int cur = ks & 1;
            uint32_t afrag[4][4];
#pragma unroll
            for (int mt = 0; mt < 4; mt++)
                ldsm_x4(afrag[mt], a_s + (uint32_t)mt * 16 * 144 + (uint32_t)ks * 32);
            if (ks < 3) LDB(cur ^ 1, b_s, ks + 1);
#pragma unroll
            for (int mt = 0; mt < 4; mt++)
#pragma unroll
                for (int nt = 0; nt < 4; nt++)
                    mma_f16(acc[mt][nt], afrag[mt], bfrag[cur][nt]);
        }
    }

    // epilogue
#pragma unroll
    for (int mt = 0; mt < 4; mt++) {
        int mrow = row0 + warp_m * 64 + mt * 16 + gid;
        if (doGelu) {
#pragma unroll
            for (int nt = 0; nt < 4; nt++) {
                int col = blockIdx.y * BN + warp_n * 32 + nt * 8 + 2 * tig;
                __half2 h0 = __floats2half2_rn(gelu_tanh(acc[mt][nt][0]),
                                               gelu_tanh(acc[mt][nt][1]));
                __half2 h1 = __floats2half2_rn(gelu_tanh(acc[mt][nt][2]),
                                               gelu_tanh(acc[mt][nt][3]));
                *(__half2*)(g_h + (size_t)mrow * Ntot + col) = h0;
                *(__half2*)(g_h + (size_t)(mrow + 8) * Ntot + col) = h1;
            }
        } else {
            int a0 = g_inv[mrow], a1 = g_inv[mrow + 8];
            float w0 = 0.f, w1 = 0.f;
            size_t o0 = 0, o1 = 0;
            if (a0 >= 0) { w0 = g_tw[a0]; o0 = (size_t)(a0 >> 1) * DDIM; }
            if (a1 >= 0) { w1 = g_tw[a1]; o1 = (size_t)(a1 >> 1) * DDIM; }
#pragma unroll
            for (int nt = 0; nt < 4; nt++) {
                int col = blockIdx.y * BN + warp_n * 32 + nt * 8 + 2 * tig;
                if (a0 >= 0) {
                    atomicAdd(out + o0 + col,     w0 * acc[mt][nt][0]);
                    atomicAdd(out + o0 + col + 1, w0 * acc[mt][nt][1]);
                }
                if (a1 >= 0) {
                    atomicAdd(out + o1 + col,     w1 * acc[mt][nt][2]);
                    atomicAdd(out + o1 + col + 1, w1 * acc[mt][nt][3]);
                }
            }
        }
    }
}

// ---------------------------------------------------------------------------
extern "C" void kernel_launch(void* const* d_in, const int* in_sizes, int n_in,
                              void* d_out, int out_size) {
    const float* x  = (const float*)d_in[0];
    const float* Wg = (const float*)d_in[1];
    const float* w1 = (const float*)d_in[2];
    const float* w2 = (const float*)d_in[3];
    float* out = (float*)d_out;

    cudaFuncSetAttribute(k_gemm_h, cudaFuncAttributeMaxDynamicSharedMemorySize, SMEM_GEMM);

    __half* w1h; cudaGetSymbolAddress((void**)&w1h, g_w1h);
    __half* w2h; cudaGetSymbolAddress((void**)&w2h, g_w2h);
    __half* xph; cudaGetSymbolAddress((void**)&xph, g_xph);
    __half* hbuf; cudaGetSymbolAddress((void**)&hbuf, g_h);

    // Launch order chosen so GEMM1 is the 6th kernel (ncu -s 5 captures it).
    k_cvt2<<<2 * CVT_N4 / 256, 256>>>((const float4*)w1, (uint2*)w1h,
                                      (const float4*)w2, (uint2*)w2h);   // 1
    k_init<<<OUT_ELEMS / 4 / 256, 256>>>((float4*)out);                  // 2
    k_gate<<<T_TOK / 8, 256>>>(x, Wg);                                   // 3
    k_offs<<<1, 32>>>();                                                 // 4
    k_gather<<<NASSIGN / 8, 256>>>(x);                                   // 5

    dim3 grid1(MAXSLOTS / BM, FDIM / BN);   // (136, 32)
    k_gemm_h<<<grid1, 256, SMEM_GEMM>>>(xph, w1h, nullptr, DDIM, FDIM, 1);  // 6

    dim3 grid2(MAXSLOTS / BM, DDIM / BN);   // (136, 8)
    k_gemm_h<<<grid2, 256, SMEM_GEMM>>>(hbuf, w2h, out, FDIM, DDIM, 0);     // 7
}

// round 16
// speedup vs baseline: 1.0264x; 1.0101x over previous
#include <cuda_runtime.h>
#include <cuda_fp16.h>
#include <cstdint>

// ---------------------------------------------------------------------------
// MoE layer: B=4,S=2048,D=1024,E=8,F=4096, top-k=2
// Round 14: fixed-capacity expert segments (no k_offs), fused gate+gather,
// cvt overlapped on a side stream (graph fork-join). GEMM identical to R13.
// ---------------------------------------------------------------------------

#define T_TOK   8192
#define DDIM    1024
#define EEXP    8
#define FDIM    4096
#define NASSIGN (T_TOK * 2)
#define CAP     2560                 // slots per expert (multiple of 128)
#define MAXSLOTS (EEXP * CAP)        // 20480
#define OUT_ELEMS (T_TOK * DDIM)     // 8388608

__device__ __half g_xph[MAXSLOTS * (size_t)DDIM];
__device__ __half g_h  [MAXSLOTS * (size_t)FDIM];
__device__ __half g_w1h[(size_t)EEXP * DDIM * FDIM];
__device__ __half g_w2h[(size_t)EEXP * FDIM * DDIM];
__device__ float g_tw[NASSIGN];
__device__ int   g_inv[MAXSLOTS];   // slot -> assignment index (-1 = pad)
__device__ int   g_cursor[EEXP];

__device__ __forceinline__ uint32_t smem_u32(const void* p) {
    uint32_t a;
    asm("{ .reg .u64 t; cvta.to.shared.u64 t, %1; cvt.u32.u64 %0, t; }" : "=r"(a) : "l"(p));
    return a;
}
#define CP_ASYNC16(dst, src) \
    asm volatile("cp.async.cg.shared.global [%0], [%1], 16;" :: "r"(dst), "l"(src) : "memory")
#define CP_COMMIT() asm volatile("cp.async.commit_group;" ::: "memory")
#define CP_WAIT(n)  asm volatile("cp.async.wait_group %0;" :: "n"(n) : "memory")

__device__ __forceinline__ void mma_f16(float* d, const uint32_t* a, const uint32_t* b) {
    asm volatile(
        "mma.sync.aligned.m16n8k16.row.col.f32.f16.f16.f32 "
        "{%0,%1,%2,%3}, {%4,%5,%6,%7}, {%8,%9}, {%0,%1,%2,%3};"
        : "+f"(d[0]), "+f"(d[1]), "+f"(d[2]), "+f"(d[3])
        : "r"(a[0]), "r"(a[1]), "r"(a[2]), "r"(a[3]), "r"(b[0]), "r"(b[1]));
}
__device__ __forceinline__ void ldsm_x4(uint32_t* r, uint32_t addr) {
    asm volatile("ldmatrix.sync.aligned.m8n8.x4.shared.b16 {%0,%1,%2,%3}, [%4];"
        : "=r"(r[0]), "=r"(r[1]), "=r"(r[2]), "=r"(r[3]) : "r"(addr));
}
__device__ __forceinline__ void ldsm_x4_t(uint32_t* r, uint32_t addr) {
    asm volatile("ldmatrix.sync.aligned.m8n8.x4.trans.shared.b16 {%0,%1,%2,%3}, [%4];"
        : "=r"(r[0]), "=r"(r[1]), "=r"(r[2]), "=r"(r[3]) : "r"(addr));
}

// ---------------------------------------------------------------------------
// Merged weight conversion: both w1 and w2 in one launch (side stream).
#define CVT_N4 (EEXP * DDIM * FDIM / 4)
__global__ void k_cvt2(const float4* __restrict__ s1, uint2* __restrict__ d1,
                       const float4* __restrict__ s2, uint2* __restrict__ d2) {
    int i = blockIdx.x * 256 + threadIdx.x;
    const float4* s = (i < CVT_N4) ? s1 : s2;
    uint2* d = (i < CVT_N4) ? d1 : d2;
    int j = (i < CVT_N4) ? i : i - CVT_N4;
    float4 v = s[j];
    __half2 h01 = __floats2half2_rn(v.x, v.y);
    __half2 h23 = __floats2half2_rn(v.z, v.w);
    uint2 u;
    u.x = *(uint32_t*)&h01;
    u.y = *(uint32_t*)&h23;
    d[j] = u;
}

// init: zero cursors, g_inv = -1, zero the output buffer.
__global__ void k_init(float4* __restrict__ out4) {
    int i = blockIdx.x * 256 + threadIdx.x;
    if (i < EEXP) g_cursor[i] = 0;
    if (i < MAXSLOTS) g_inv[i] = -1;
    if (i < OUT_ELEMS / 4) out4[i] = make_float4(0.f, 0.f, 0.f, 0.f);
}

// Fused gate + gather: one warp per token. Computes top-2 softmax routing,
// claims slots in fixed-capacity expert regions, writes both fp16 rows.
__global__ void k_gatego(const float* __restrict__ x, const float* __restrict__ Wg) {
    int t = blockIdx.x * 8 + (threadIdx.x >> 5);
    int lane = threadIdx.x & 31;
    const float* xr = x + (size_t)t * DDIM;

    float acc[EEXP];
#pragma unroll
    for (int e = 0; e < EEXP; e++) acc[e] = 0.f;
#pragma unroll 4
    for (int i = 0; i < DDIM / 32; i++) {
        int d = i * 32 + lane;
        float xv = xr[d];
        const float4* wr = (const float4*)(Wg + (size_t)d * EEXP);
        float4 w0 = wr[0], w1 = wr[1];
        acc[0] += xv * w0.x; acc[1] += xv * w0.y;
        acc[2] += xv * w0.z; acc[3] += xv * w0.w;
        acc[4] += xv * w1.x; acc[5] += xv * w1.y;
        acc[6] += xv * w1.z; acc[7] += xv * w1.w;
    }
#pragma unroll
    for (int off = 16; off > 0; off >>= 1)
#pragma unroll
        for (int e = 0; e < EEXP; e++)
            acc[e] += __shfl_xor_sync(0xffffffffu, acc[e], off);

    int slot0 = 0, slot1 = 0;
    if (lane == 0) {
        int i1 = 0;
#pragma unroll
        for (int e = 1; e < EEXP; e++) if (acc[e] > acc[i1]) i1 = e;
        int i2 = -1;
#pragma unroll
        for (int e = 0; e < EEXP; e++) {
            if (e == i1) continue;
            if (i2 < 0 || acc[e] > acc[i2]) i2 = e;
        }
        float wa = 1.f / (1.f + expf(acc[i2] - acc[i1]));
        g_tw[2 * t]     = wa;
        g_tw[2 * t + 1] = 1.f - wa;
        slot0 = i1 * CAP + atomicAdd(&g_cursor[i1], 1);
        slot1 = i2 * CAP + atomicAdd(&g_cursor[i2], 1);
        g_inv[slot0] = 2 * t;
        g_inv[slot1] = 2 * t + 1;
    }
    slot0 = __shfl_sync(0xffffffffu, slot0, 0);
    slot1 = __shfl_sync(0xffffffffu, slot1, 0);

    const float4* src = (const float4*)xr;
    uint2* d0 = (uint2*)(g_xph + (size_t)slot0 * DDIM);
    uint2* d1 = (uint2*)(g_xph + (size_t)slot1 * DDIM);
#pragma unroll
    for (int i = 0; i < 8; i++) {
        float4 v = src[lane + 32 * i];
        __half2 h01 = __floats2half2_rn(v.x, v.y);
        __half2 h23 = __floats2half2_rn(v.z, v.w);
        uint2 u;
        u.x = *(uint32_t*)&h01;
        u.y = *(uint32_t*)&h23;
        d0[lane + 32 * i] = u;
        d1[lane + 32 * i] = u;
    }
}

__device__ __forceinline__ float gelu_tanh(float v) {
    float v3 = v * v * v;
    return 0.5f * v * (1.f + tanhf(0.7978845608028654f * (v + 0.044715f * v3)));
}

// ---------------------------------------------------------------------------
// fp16 mma GEMM, 256 threads, 2 CTAs/SM. BM=128, BN=128, BK=64 halves.
#define BM 128
#define BN 128
#define BKF 64
#define NSTAGE 2
#define ATILE_B (BM * 72 * 2)        // 18432 B
#define BTILE_B (BKF * 136 * 2)      // 17408 B
#define SMEM_GEMM (NSTAGE * (ATILE_B + BTILE_B))  // 71680 B

__global__ __launch_bounds__(256, 2)
void k_gemm_h(const __half* __restrict__ A, const __half* __restrict__ W,
              float* __restrict__ out, int K, int Ntot, int doGelu) {
    int row0 = blockIdx.x * BM;
    int e = row0 / CAP;
    int local = row0 - e * CAP;
    if (local >= g_cursor[e]) return;   // tile entirely pad

    extern __shared__ char smem[];
    uint32_t sbase = smem_u32(smem);

    int tid = threadIdx.x, wid = tid >> 5, lane = tid & 31;
    int gid = lane >> 2, tig = lane & 3;
    int warp_m = wid & 1, warp_n = wid >> 1;   // 2 x 4 warps, warp tile 64x32

    const __half* B = W + (size_t)e * K * Ntot + (size_t)blockIdx.y * BN;

    int ar = tid >> 3, ach = tid & 7;
    const __half* asrc = A + (size_t)(row0 + ar) * K + ach * 8;
    uint32_t a_d = sbase + (uint32_t)ar * 144 + (uint32_t)ach * 16;
    int br = tid >> 4, bch = tid & 15;
    const __half* bsrc = B + (size_t)br * Ntot + bch * 8;
    uint32_t b_d = sbase + (uint32_t)NSTAGE * ATILE_B + (uint32_t)br * 272 + (uint32_t)bch * 16;

    uint32_t a_lm = sbase + ((uint32_t)(warp_m * 64 + (lane & 15))) * 144 + ((lane >> 4) << 4);
    uint32_t b_row = (lane & 7) + ((lane >> 3) & 1) * 8;
    uint32_t b_ncol = (uint32_t)(warp_n * 32) + ((lane >> 4) << 3);
    uint32_t b_lm = sbase + (uint32_t)NSTAGE * ATILE_B + b_row * 272 + b_ncol * 2;

    float acc[4][4][4];
#pragma unroll
    for (int mt = 0; mt < 4; mt++)
#pragma unroll
        for (int nt = 0; nt < 4; nt++)
#pragma unroll
            for (int j = 0; j < 4; j++) acc[mt][nt][j] = 0.f;

    int KT = K / BKF;

#define LOAD_TILE(kt, st) do { \
    int _k0 = (kt) * BKF; \
    uint32_t _ao = (uint32_t)(st) * ATILE_B; \
    uint32_t _bo = (uint32_t)(st) * BTILE_B; \
    CP_ASYNC16(a_d + _ao,                  asrc + _k0); \
    CP_ASYNC16(a_d + _ao + 32u * 144,      asrc + _k0 + (size_t)32 * K); \
    CP_ASYNC16(a_d + _ao + 64u * 144,      asrc + _k0 + (size_t)64 * K); \
    CP_ASYNC16(a_d + _ao + 96u * 144,      asrc + _k0 + (size_t)96 * K); \
    CP_ASYNC16(b_d + _bo,                  bsrc + (size_t)_k0 * Ntot); \
    CP_ASYNC16(b_d + _bo + 16u * 272,      bsrc + (size_t)(_k0 + 16) * Ntot); \
    CP_ASYNC16(b_d + _bo + 32u * 272,      bsrc + (size_t)(_k0 + 32) * Ntot); \
    CP_ASYNC16(b_d + _bo + 48u * 272,      bsrc + (size_t)(_k0 + 48) * Ntot); \
} while (0)

#define LDB(buf, b_s, ks) do { \
    _Pragma("unroll") \
    for (int _n2 = 0; _n2 < 2; _n2++) { \
        uint32_t _r[4]; \
        ldsm_x4_t(_r, (b_s) + (uint32_t)(ks) * 16 * 272 + (uint32_t)_n2 * 32); \
        bfrag[buf][2 * _n2][0] = _r[0]; bfrag[buf][2 * _n2][1] = _r[1]; \
        bfrag[buf][2 * _n2 + 1][0] = _r[2]; bfrag[buf][2 * _n2 + 1][1] = _r[3]; \
    } \
} while (0)

    LOAD_TILE(0, 0); CP_COMMIT();

    uint32_t bfrag[2][4][2];

    for (int kt = 0; kt < KT; kt++) {
        int stage = kt & 1;
        CP_WAIT(0);
        __syncthreads();
        if (kt + 1 < KT) {
            LOAD_TILE(kt + 1, stage ^ 1);
            CP_COMMIT();
        }

        uint32_t a_s = a_lm + (uint32_t)stage * ATILE_B;
        uint32_t b_s = b_lm + (uint32_t)stage * BTILE_B;

        LDB(0, b_s, 0);
#pragma unroll
        for (int ks = 0; ks < 4; ks++) {
            int cur = ks & 1;
            uint32_t afrag[4][4];
#pragma unroll
            for (int mt = 0; mt < 4; mt++)
                ldsm_x4(afrag[mt], a_s + (uint32_t)mt * 16 * 144 + (uint32_t)ks * 32);
            if (ks < 3) LDB(cur ^ 1, b_s, ks + 1);
#pragma unroll
            for (int mt = 0; mt < 4; mt++)
#pragma unroll
                for (int nt = 0; nt < 4; nt++)
                    mma_f16(acc[mt][nt], afrag[mt], bfrag[cur][nt]);
        }
    }

    // epilogue
#pragma unroll
    for (int mt = 0; mt < 4; mt++) {
        int mrow = row0 + warp_m * 64 + mt * 16 + gid;
        if (doGelu) {
#pragma unroll
            for (int nt = 0; nt < 4; nt++) {
                int col = blockIdx.y * BN + warp_n * 32 + nt * 8 + 2 * tig;
                __half2 h0 = __floats2half2_rn(gelu_tanh(acc[mt][nt][0]),
                                               gelu_tanh(acc[mt][nt][1]));
                __half2 h1 = __floats2half2_rn(gelu_tanh(acc[mt][nt][2]),
                                               gelu_tanh(acc[mt][nt][3]));
                *(__half2*)(g_h + (size_t)mrow * Ntot + col) = h0;
                *(__half2*)(g_h + (size_t)(mrow + 8) * Ntot + col) = h1;
            }
        } else {
            int a0 = g_inv[mrow], a1 = g_inv[mrow + 8];
            float w0 = 0.f, w1 = 0.f;
            size_t o0 = 0, o1 = 0;
            if (a0 >= 0) { w0 = g_tw[a0]; o0 = (size_t)(a0 >> 1) * DDIM; }
            if (a1 >= 0) { w1 = g_tw[a1]; o1 = (size_t)(a1 >> 1) * DDIM; }
#pragma unroll
            for (int nt = 0; nt < 4; nt++) {
                int col = blockIdx.y * BN + warp_n * 32 + nt * 8 + 2 * tig;
                if (a0 >= 0) {
                    atomicAdd(out + o0 + col,     w0 * acc[mt][nt][0]);
                    atomicAdd(out + o0 + col + 1, w0 * acc[mt][nt][1]);
                }
                if (a1 >= 0) {
                    atomicAdd(out + o1 + col,     w1 * acc[mt][nt][2]);
                    atomicAdd(out + o1 + col + 1, w1 * acc[mt][nt][3]);
                }
            }
        }
    }
}

// ---------------------------------------------------------------------------
extern "C" void kernel_launch(void* const* d_in, const int* in_sizes, int n_in,
                              void* d_out, int out_size) {
    const float* x  = (const float*)d_in[0];
    const float* Wg = (const float*)d_in[1];
    const float* w1 = (const float*)d_in[2];
    const float* w2 = (const float*)d_in[3];
    float* out = (float*)d_out;

    cudaFuncSetAttribute(k_gemm_h, cudaFuncAttributeMaxDynamicSharedMemorySize, SMEM_GEMM);

    __half* w1h; cudaGetSymbolAddress((void**)&w1h, g_w1h);
    __half* w2h; cudaGetSymbolAddress((void**)&w2h, g_w2h);
    __half* xph; cudaGetSymbolAddress((void**)&xph, g_xph);
    __half* hbuf; cudaGetSymbolAddress((void**)&hbuf, g_h);

    // Fork: weight conversion on a side stream, overlapped with init+gate.
    cudaStream_t s2;
    cudaStreamCreateWithFlags(&s2, cudaStreamNonBlocking);
    cudaEvent_t ev1, ev2;
    cudaEventCreateWithFlags(&ev1, cudaEventDisableTiming);
    cudaEventCreateWithFlags(&ev2, cudaEventDisableTiming);

    cudaEventRecord(ev1, 0);
    cudaStreamWaitEvent(s2, ev1, 0);
    k_cvt2<<<2 * CVT_N4 / 256, 256, 0, s2>>>((const float4*)w1, (uint2*)w1h,
                                             (const float4*)w2, (uint2*)w2h);
    cudaEventRecord(ev2, s2);

    k_init<<<OUT_ELEMS / 4 / 256, 256>>>((float4*)out);
    k_gatego<<<T_TOK / 8, 256>>>(x, Wg);

    cudaStreamWaitEvent(0, ev2, 0);

    dim3 grid1(MAXSLOTS / BM, FDIM / BN);   // (160, 32)
    k_gemm_h<<<grid1, 256, SMEM_GEMM>>>(xph, w1h, nullptr, DDIM, FDIM, 1);

    dim3 grid2(MAXSLOTS / BM, DDIM / BN);   // (160, 8)
    k_gemm_h<<<grid2, 256, SMEM_GEMM>>>(hbuf, w2h, out, FDIM, DDIM, 0);
}